// round 1
// baseline (speedup 1.0000x reference)
#include <cuda_runtime.h>
#include <cstdint>
#include <cstddef>

#define NMAX 100000
#define EMAX 1600000
#define GMAX 64

// -------- device scratch (static globals; no allocation allowed) --------
__device__ float g_h[(size_t)NMAX * 128];   // ping
__device__ float g_t[(size_t)NMAX * 128];   // pong
__device__ int2  g_edges[EMAX];             // {src, norm-as-int}
__device__ int   g_rowstart[NMAX + 1];
__device__ int   g_cursor[NMAX];
__device__ int   g_hist[NMAX];
__device__ float g_dinv[NMAX];
__device__ float g_pool[GMAX * 16];
__device__ float g_cnt[GMAX];
__device__ int   g_is64;

// -------- index dtype handling (int64 vs int32 edge_index/batch) --------
__device__ __forceinline__ int load_idx(const void* p, int i, int is64) {
    if (is64) return (int)__ldg((const long long*)p + i);
    return __ldg((const int*)p + i);
}

// Detect: if data is int64 (values < 2^31), every odd int32 word is 0.
__global__ void k_detect(const void* ei) {
    const int* p = (const int*)ei;
    int t = threadIdx.x;              // 32 threads
    int v = p[2 * t + 1];
    unsigned any = __ballot_sync(0xffffffffu, v != 0);
    if (t == 0) g_is64 = (any == 0) ? 1 : 0;
}

__global__ void k_init(int n) {
    int i = blockIdx.x * blockDim.x + threadIdx.x;
    if (i < n) g_hist[i] = 0;
    if (i < GMAX * 16) g_pool[i] = 0.f;
    if (i < GMAX) g_cnt[i] = 0.f;
}

__global__ void k_hist(const void* ei, int E) {
    int e = blockIdx.x * blockDim.x + threadIdx.x;
    if (e >= E) return;
    int is64 = g_is64;
    int d = load_idx(ei, E + e, is64);
    atomicAdd(&g_hist[d], 1);
}

__global__ void k_dinv(int n) {
    int v = blockIdx.x * blockDim.x + threadIdx.x;
    if (v >= n) return;
    g_dinv[v] = rsqrtf((float)(g_hist[v] + 1));   // +1 self loop; always > 0
}

// single-block exclusive scan of g_hist -> g_rowstart (+ copy to g_cursor)
__global__ void k_scan(int n) {
    __shared__ int sh[1024];
    int t = threadIdx.x;
    int chunk = (n + 1023) >> 10;
    int lo = t * chunk;
    int hi = min(lo + chunk, n);
    int s = 0;
    for (int i = lo; i < hi; i++) s += g_hist[i];
    sh[t] = s;
    __syncthreads();
    for (int off = 1; off < 1024; off <<= 1) {
        int v = (t >= off) ? sh[t - off] : 0;
        __syncthreads();
        sh[t] += v;
        __syncthreads();
    }
    int run = sh[t] - s;  // exclusive prefix
    for (int i = lo; i < hi; i++) {
        int c = g_hist[i];
        g_rowstart[i] = run;
        g_cursor[i]   = run;
        run += c;
    }
    if (t == 1023) g_rowstart[n] = run;   // == E
}

__global__ void k_scatter(const void* ei, int E) {
    int e = blockIdx.x * blockDim.x + threadIdx.x;
    if (e >= E) return;
    int is64 = g_is64;
    int s = load_idx(ei, e, is64);
    int d = load_idx(ei, E + e, is64);
    int pos = atomicAdd(&g_cursor[d], 1);
    float nrm = g_dinv[s] * g_dinv[d];
    g_edges[pos] = make_int2(s, __float_as_int(nrm));
}

// layer-0 pre-aggregation at input dim 3 (Agg(x)); writes g_t stride 4
__global__ void k_agg0(const float* __restrict__ x, int n) {
    int v = blockIdx.x * blockDim.x + threadIdx.x;
    if (v >= n) return;
    int s0 = g_rowstart[v], s1 = g_rowstart[v + 1];
    float a0 = 0.f, a1 = 0.f, a2 = 0.f;
    for (int e = s0; e < s1; e++) {
        int2 ed = g_edges[e];
        float w = __int_as_float(ed.y);
        const float* xr = x + 3 * ed.x;
        a0 += w * xr[0]; a1 += w * xr[1]; a2 += w * xr[2];
    }
    float dv = g_dinv[v];
    float ws = dv * dv;
    const float* xr = x + 3 * v;
    a0 += ws * xr[0]; a1 += ws * xr[1]; a2 += ws * xr[2];
    *(float4*)(g_t + 4 * (size_t)v) = make_float4(a0, a1, a2, 0.f);
}

// layer 0 GEMM: [N,3(pad4)] @ W0[3,128] + b0, relu -> g_h
__global__ void k_gemm0(const float* __restrict__ W0, const float* __restrict__ b0, int n) {
    __shared__ float Ws[3 * 128];
    __shared__ float bs[128];
    int tid = threadIdx.x;
    for (int i = tid; i < 384; i += 256) Ws[i] = W0[i];
    for (int i = tid; i < 128; i += 256) bs[i] = b0[i];
    __syncthreads();
    int gid = blockIdx.x * 256 + tid;
    int v = gid >> 5, cg = gid & 31;
    if (v >= n) return;
    float4 a = *(const float4*)(g_t + 4 * (size_t)v);
    float o[4];
#pragma unroll
    for (int c = 0; c < 4; c++) {
        int j = cg * 4 + c;
        float acc = bs[j] + a.x * Ws[j] + a.y * Ws[128 + j] + a.z * Ws[256 + j];
        o[c] = fmaxf(acc, 0.f);
    }
    *(float4*)(g_h + (size_t)v * 128 + cg * 4) = make_float4(o[0], o[1], o[2], o[3]);
}

// generic GEMM: out[N,FOUT] = scale * in[N,FIN] @ W[FIN,FOUT]  (no bias/relu)
template <int FIN, int FOUT, int NPT>
__global__ void __launch_bounds__(128)
k_gemm(const float* __restrict__ in, const float* __restrict__ Wg,
       float* __restrict__ outp, int n, float scale) {
    constexpr int T = 128;
    constexpr int NODES = T * NPT;
    constexpr int KC = 8;
    __shared__ float Ws[FIN * FOUT];
    __shared__ float Hs[KC][NODES];
    for (int i = threadIdx.x; i < FIN * FOUT; i += T) Ws[i] = Wg[i];
    int base = blockIdx.x * NODES;
    float acc[NPT * FOUT];
#pragma unroll
    for (int i = 0; i < NPT * FOUT; i++) acc[i] = 0.f;

    for (int k0 = 0; k0 < FIN; k0 += KC) {
        __syncthreads();
        constexpr int NF4 = NODES * KC / 4;
        constexpr int RPT = NF4 / T;
#pragma unroll
        for (int r = 0; r < RPT; r++) {
            int i = threadIdx.x + r * T;
            int nd = i / (KC / 4), q = i % (KC / 4);
            int gv = base + nd;
            float4 val = make_float4(0.f, 0.f, 0.f, 0.f);
            if (gv < n) val = *(const float4*)(in + (size_t)gv * FIN + k0 + q * 4);
            Hs[q * 4 + 0][nd] = val.x;
            Hs[q * 4 + 1][nd] = val.y;
            Hs[q * 4 + 2][nd] = val.z;
            Hs[q * 4 + 3][nd] = val.w;
        }
        __syncthreads();
#pragma unroll
        for (int kk = 0; kk < KC; kk++) {
            float hk[NPT];
            if constexpr (NPT == 2) {
                float2 h2 = *(const float2*)&Hs[kk][threadIdx.x * 2];
                hk[0] = h2.x; hk[1] = h2.y;
            } else {
                float4 h4 = *(const float4*)&Hs[kk][threadIdx.x * 4];
                hk[0] = h4.x; hk[1] = h4.y; hk[2] = h4.z; hk[3] = h4.w;
            }
            const float4* wr = (const float4*)&Ws[(k0 + kk) * FOUT];
#pragma unroll
            for (int j4 = 0; j4 < FOUT / 4; j4++) {
                float4 w = wr[j4];
#pragma unroll
                for (int p = 0; p < NPT; p++) {
                    acc[p * FOUT + j4 * 4 + 0] += hk[p] * w.x;
                    acc[p * FOUT + j4 * 4 + 1] += hk[p] * w.y;
                    acc[p * FOUT + j4 * 4 + 2] += hk[p] * w.z;
                    acc[p * FOUT + j4 * 4 + 3] += hk[p] * w.w;
                }
            }
        }
    }
#pragma unroll
    for (int p = 0; p < NPT; p++) {
        int gv = base + threadIdx.x * NPT + p;
        if (gv < n) {
            float4* o = (float4*)(outp + (size_t)gv * FOUT);
#pragma unroll
            for (int j4 = 0; j4 < FOUT / 4; j4++)
                o[j4] = make_float4(scale * acc[p * FOUT + j4 * 4 + 0],
                                    scale * acc[p * FOUT + j4 * 4 + 1],
                                    scale * acc[p * FOUT + j4 * 4 + 2],
                                    scale * acc[p * FOUT + j4 * 4 + 3]);
        }
    }
}

// aggregation (CSR gather, warp per node): out = relu(Agg(t) + bias)
template <int F>
__global__ void k_agg(const float* __restrict__ tin, const float* __restrict__ bias,
                      float* __restrict__ outp, int n) {
    int gid = blockIdx.x * blockDim.x + threadIdx.x;
    int v = gid >> 5, lane = gid & 31;
    if (v >= n) return;
    int s0 = g_rowstart[v], s1 = g_rowstart[v + 1];
    float dv = g_dinv[v];
    float ws = dv * dv;
    if constexpr (F == 64) {
        const float2* t2 = (const float2*)tin;
        float2 acc = make_float2(0.f, 0.f);
        for (int e = s0; e < s1; e++) {
            int2 ed = g_edges[e];
            float w = __int_as_float(ed.y);
            float2 hv = t2[(size_t)ed.x * 32 + lane];
            acc.x += w * hv.x; acc.y += w * hv.y;
        }
        float2 hv = t2[(size_t)v * 32 + lane];
        acc.x += ws * hv.x; acc.y += ws * hv.y;
        float bx = bias[2 * lane], by = bias[2 * lane + 1];
        *(float2*)(outp + (size_t)v * 64 + 2 * lane) =
            make_float2(fmaxf(acc.x + bx, 0.f), fmaxf(acc.y + by, 0.f));
    } else {
        if (lane < F) {
            float acc = 0.f;
            for (int e = s0; e < s1; e++) {
                int2 ed = g_edges[e];
                float w = __int_as_float(ed.y);
                acc += w * tin[(size_t)ed.x * F + lane];
            }
            acc += ws * tin[(size_t)v * F + lane];
            outp[(size_t)v * F + lane] = fmaxf(acc + bias[lane], 0.f);
        }
    }
}

__global__ void k_pool(const void* batch, int n) {
    int v = blockIdx.x * blockDim.x + threadIdx.x;
    if (v >= n) return;
    int is64 = g_is64;
    int g = load_idx(batch, v, is64);
    const float* hr = g_h + (size_t)v * 16;
#pragma unroll
    for (int j = 0; j < 16; j++) atomicAdd(&g_pool[g * 16 + j], hr[j]);
    atomicAdd(&g_cnt[g], 1.f);
}

__global__ void k_final(const float* __restrict__ fc1w, const float* __restrict__ fc1b,
                        const float* __restrict__ fc2w, const float* __restrict__ fc2b,
                        float* __restrict__ out, int G) {
    int g = threadIdx.x;
    if (g >= G) return;
    float c = fmaxf(g_cnt[g], 1.f);
    float p[16];
#pragma unroll
    for (int j = 0; j < 16; j++) p[j] = g_pool[g * 16 + j] / c;
    float z[8];
#pragma unroll
    for (int i = 0; i < 8; i++) {
        float a = fc1b[i];
#pragma unroll
        for (int j = 0; j < 16; j++) a += p[j] * fc1w[j * 8 + i];
        z[i] = fmaxf(a, 0.f);
    }
#pragma unroll
    for (int o = 0; o < 4; o++) {
        float a = fc2b[o];
#pragma unroll
        for (int i = 0; i < 8; i++) a += z[i] * fc2w[i * 4 + o];
        out[g * 4 + o] = a;
    }
}

// ------------------------------- host -------------------------------
extern "C" void kernel_launch(void* const* d_in, const int* in_sizes, int n_in,
                              void* d_out, int out_size) {
    const float* x    = (const float*)d_in[0];
    const void*  ei   = d_in[1];
    const void*  bat  = d_in[2];
    const float* W0 = (const float*)d_in[3];  const float* b0 = (const float*)d_in[4];
    const float* W1 = (const float*)d_in[5];  const float* b1 = (const float*)d_in[6];
    const float* W2 = (const float*)d_in[7];  const float* b2 = (const float*)d_in[8];
    const float* W3 = (const float*)d_in[9];  const float* b3 = (const float*)d_in[10];
    const float* fc1w = (const float*)d_in[11]; const float* fc1b = (const float*)d_in[12];
    const float* fc2w = (const float*)d_in[13]; const float* fc2b = (const float*)d_in[14];
    float* out = (float*)d_out;

    int N = in_sizes[0] / 3;
    int E = in_sizes[1] / 2;
    int G = out_size / 4;
    if (N > NMAX || E > EMAX || G > GMAX) return;

    void *ph = nullptr, *pt = nullptr;
    cudaGetSymbolAddress(&ph, g_h);
    cudaGetSymbolAddress(&pt, g_t);
    float* H = (float*)ph;
    float* T = (float*)pt;

    int gN = (N + 255) / 256;
    int gE = (E + 255) / 256;
    int gW = (N * 32 + 255) / 256;   // warp-per-node kernels

    k_detect<<<1, 32>>>(ei);
    k_init<<<gN, 256>>>(N);
    k_hist<<<gE, 256>>>(ei, E);
    k_dinv<<<gN, 256>>>(N);
    k_scan<<<1, 1024>>>(N);
    k_scatter<<<gE, 256>>>(ei, E);

    // layer 0: aggregate at dim 3, then GEMM(+bias+relu)
    k_agg0<<<gN, 256>>>(x, N);
    k_gemm0<<<gW, 256>>>(W0, b0, N);

    // layer 1: t = 2*(h @ W1) ; h = relu(Agg(t) + b1)
    k_gemm<128, 64, 2><<<(N + 255) / 256, 128>>>(H, W1, T, N, 2.f);
    k_agg<64><<<gW, 256>>>(T, b1, H, N);

    // layer 2
    k_gemm<64, 32, 4><<<(N + 511) / 512, 128>>>(H, W2, T, N, 2.f);
    k_agg<32><<<gW, 256>>>(T, b2, H, N);

    // layer 3
    k_gemm<32, 16, 4><<<(N + 511) / 512, 128>>>(H, W3, T, N, 2.f);
    k_agg<16><<<gW, 256>>>(T, b3, H, N);

    // pooling + MLP head
    k_pool<<<gN, 256>>>(bat, N);
    k_final<<<1, 64>>>(fc1w, fc1b, fc2w, fc2b, out, G);
}

// round 2
// speedup vs baseline: 2.4567x; 2.4567x over previous
#include <cuda_runtime.h>
#include <cstdint>
#include <cstddef>

#define NMAX 100000
#define EMAX 1600000
#define GMAX 64
#define NB_MAX 128

// -------- device scratch --------
__device__ float g_h[(size_t)NMAX * 64];   // t2 (N x 32)
__device__ float g_t[(size_t)NMAX * 64];   // t1 (N x 64), later t3 (N x 16)
__device__ float g_a[(size_t)NMAX * 4];    // aggregated x (N x 4)
__device__ int2  g_edges[EMAX];            // {src, norm-as-float-bits}, grouped by dst
__device__ int   g_rowstart[NMAX + 1];
__device__ int   g_cursor[NMAX];
__device__ int   g_hist[NMAX];
__device__ float g_dinv[NMAX];
__device__ float g_pool[GMAX * 16];
__device__ float g_cnt[GMAX];
__device__ int   g_bsum[NB_MAX];
__device__ int   g_boff[NB_MAX];
__device__ int   g_is64;

__device__ __forceinline__ int load_idx(const void* p, int i, int is64) {
    if (is64) return (int)__ldg((const long long*)p + i);
    return __ldg((const int*)p + i);
}

// init hist/pool/cnt + dtype detection (int64 has zero high words)
__global__ void k_init(const void* ei, int n) {
    int i = blockIdx.x * blockDim.x + threadIdx.x;
    if (i < n) g_hist[i] = 0;
    if (i < GMAX * 16) g_pool[i] = 0.f;
    if (i < GMAX) g_cnt[i] = 0.f;
    if (blockIdx.x == 0 && threadIdx.x < 32) {
        const int* p = (const int*)ei;
        int v = p[2 * threadIdx.x + 1];
        unsigned any = __ballot_sync(0xffffffffu, v != 0);
        if (threadIdx.x == 0) g_is64 = (any == 0) ? 1 : 0;
    }
}

__global__ void k_hist(const void* ei, int E) {
    int e = blockIdx.x * blockDim.x + threadIdx.x;
    if (e >= E) return;
    int d = load_idx(ei, E + e, g_is64);
    atomicAdd(&g_hist[d], 1);
}

// ---- 3-phase scan (block=256, 1024 elems/block) ----
__global__ void k_scan1(int n) {
    __shared__ int sh[256];
    int base = blockIdx.x * 1024 + threadIdx.x * 4;
    int s = 0;
#pragma unroll
    for (int q = 0; q < 4; q++) { int i = base + q; if (i < n) s += g_hist[i]; }
    sh[threadIdx.x] = s;
    __syncthreads();
    for (int off = 128; off > 0; off >>= 1) {
        if (threadIdx.x < off) sh[threadIdx.x] += sh[threadIdx.x + off];
        __syncthreads();
    }
    if (threadIdx.x == 0) g_bsum[blockIdx.x] = sh[0];
}

__global__ void k_scan2(int nb, int n) {
    __shared__ int sh[128];
    int t = threadIdx.x;
    int v = (t < nb) ? g_bsum[t] : 0;
    sh[t] = v;
    __syncthreads();
    for (int off = 1; off < 128; off <<= 1) {
        int u = (t >= off) ? sh[t - off] : 0;
        __syncthreads();
        sh[t] += u;
        __syncthreads();
    }
    if (t < nb) g_boff[t] = sh[t] - v;
    if (t == nb - 1) g_rowstart[n] = sh[t];   // == E
}

__global__ void k_scan3(int n) {
    __shared__ int sh[256];
    int t = threadIdx.x;
    int base = blockIdx.x * 1024 + t * 4;
    int h[4]; int s = 0;
#pragma unroll
    for (int q = 0; q < 4; q++) { int i = base + q; h[q] = (i < n) ? g_hist[i] : 0; s += h[q]; }
    sh[t] = s;
    __syncthreads();
    for (int off = 1; off < 256; off <<= 1) {
        int u = (t >= off) ? sh[t - off] : 0;
        __syncthreads();
        sh[t] += u;
        __syncthreads();
    }
    int off0 = g_boff[blockIdx.x] + sh[t] - s;
#pragma unroll
    for (int q = 0; q < 4; q++) {
        int i = base + q;
        if (i < n) {
            g_rowstart[i] = off0;
            g_cursor[i]   = off0;
            g_dinv[i]     = rsqrtf((float)(h[q] + 1));
            off0 += h[q];
        }
    }
}

__global__ void k_scatter(const void* ei, int E) {
    int e = blockIdx.x * blockDim.x + threadIdx.x;
    if (e >= E) return;
    int is64 = g_is64;
    int s = load_idx(ei, e, is64);
    int d = load_idx(ei, E + e, is64);
    int pos = atomicAdd(&g_cursor[d], 1);
    g_edges[pos] = make_int2(s, __float_as_int(g_dinv[s] * g_dinv[d]));
}

// aggregate x at dim 3 -> g_a (stride 4)
__global__ void k_agg0(const float* __restrict__ x, int n) {
    int v = blockIdx.x * blockDim.x + threadIdx.x;
    if (v >= n) return;
    int s0 = g_rowstart[v], s1 = g_rowstart[v + 1];
    float a0 = 0.f, a1 = 0.f, a2 = 0.f, b0 = 0.f, b1 = 0.f, b2 = 0.f;
    int e = s0;
    for (; e + 1 < s1; e += 2) {
        int2 ea = g_edges[e], eb = g_edges[e + 1];
        float wa = __int_as_float(ea.y), wb = __int_as_float(eb.y);
        const float* xa = x + 3 * (size_t)ea.x;
        const float* xb = x + 3 * (size_t)eb.x;
        a0 += wa * xa[0]; a1 += wa * xa[1]; a2 += wa * xa[2];
        b0 += wb * xb[0]; b1 += wb * xb[1]; b2 += wb * xb[2];
    }
    if (e < s1) {
        int2 ea = g_edges[e];
        float wa = __int_as_float(ea.y);
        const float* xa = x + 3 * (size_t)ea.x;
        a0 += wa * xa[0]; a1 += wa * xa[1]; a2 += wa * xa[2];
    }
    float dv = g_dinv[v], ws = dv * dv;
    const float* xr = x + 3 * (size_t)v;
    *(float4*)(g_a + 4 * (size_t)v) =
        make_float4(a0 + b0 + ws * xr[0], a1 + b1 + ws * xr[1], a2 + b2 + ws * xr[2], 0.f);
}

// fused layers 0+1: t1[v] = 2 * relu(aggx[v]·W0 + b0) · W1   (h0 never materialized)
// 128 threads, 256 nodes/block. thread = (t6 in 0..63 -> 4 nodes) x (jh in 0..1 -> 32 outs)
__global__ void __launch_bounds__(128)
k_l01(const float* __restrict__ W0, const float* __restrict__ b0,
      const float* __restrict__ W1, int n) {
    __shared__ float4 W0c[128];
    __shared__ float  W1s[128 * 64];
    int tid = threadIdx.x;
    W0c[tid] = make_float4(W0[tid], W0[128 + tid], W0[256 + tid], b0[tid]);
    for (int i = tid; i < 128 * 64; i += 128) W1s[i] = W1[i];
    __syncthreads();
    int t6 = tid & 63, jh = tid >> 6;
    int base = blockIdx.x * 256 + t6 * 4;
    float4 a[4];
#pragma unroll
    for (int p = 0; p < 4; p++) {
        int v = base + p;
        a[p] = (v < n) ? *(const float4*)(g_a + 4 * (size_t)v) : make_float4(0, 0, 0, 0);
    }
    float acc[4][32];
#pragma unroll
    for (int p = 0; p < 4; p++)
#pragma unroll
        for (int q = 0; q < 32; q++) acc[p][q] = 0.f;

    const float4* W1s4 = (const float4*)W1s;
    for (int k = 0; k < 128; k++) {
        float4 wc = W0c[k];
        float hh[4];
#pragma unroll
        for (int p = 0; p < 4; p++)
            hh[p] = fmaxf(fmaf(a[p].x, wc.x, fmaf(a[p].y, wc.y, fmaf(a[p].z, wc.z, wc.w))), 0.f);
        const float4* wr = W1s4 + k * 16 + jh * 8;
#pragma unroll
        for (int q = 0; q < 8; q++) {
            float4 w = wr[q];
#pragma unroll
            for (int p = 0; p < 4; p++) {
                acc[p][q * 4 + 0] += hh[p] * w.x;
                acc[p][q * 4 + 1] += hh[p] * w.y;
                acc[p][q * 4 + 2] += hh[p] * w.z;
                acc[p][q * 4 + 3] += hh[p] * w.w;
            }
        }
    }
#pragma unroll
    for (int p = 0; p < 4; p++) {
        int v = base + p;
        if (v < n) {
            float4* o = (float4*)(g_t + (size_t)v * 64 + jh * 32);
#pragma unroll
            for (int q = 0; q < 8; q++)
                o[q] = make_float4(2.f * acc[p][q * 4 + 0], 2.f * acc[p][q * 4 + 1],
                                   2.f * acc[p][q * 4 + 2], 2.f * acc[p][q * 4 + 3]);
        }
    }
}

// fused agg + GEMM: h = relu(Agg(tin) + bias) (64-node tile in smem); out = 2 * h @ W
template <int FIN, int FOUT>
__global__ void __launch_bounds__(256)
k_fused(const float* __restrict__ tin, const float* __restrict__ bias,
        const float* __restrict__ Wg, float* __restrict__ outp, int n) {
    constexpr int STR = FIN + 1;
    __shared__ float Hs[64 * STR];
    __shared__ float Ws[FIN * FOUT];
    __shared__ float bs[FIN];
    int tid = threadIdx.x;
    for (int i = tid; i < FIN * FOUT; i += 256) Ws[i] = Wg[i];
    if (tid < FIN) bs[tid] = bias[tid];
    int w = tid >> 5, lane = tid & 31;
    int base = blockIdx.x * 64;

    // Phase A: warp-per-node aggregation into smem
    if constexpr (FIN == 64) {
        const float2* t2 = (const float2*)tin;
        for (int i = 0; i < 8; i++) {
            int v = base + w * 8 + i;
            if (v >= n) break;
            int s0 = g_rowstart[v], s1 = g_rowstart[v + 1];
            float dv = g_dinv[v], ws = dv * dv;
            float2 a0 = make_float2(0.f, 0.f), a1 = make_float2(0.f, 0.f);
            int e = s0;
            for (; e + 1 < s1; e += 2) {
                int2 ea = g_edges[e], eb = g_edges[e + 1];
                float2 ha = t2[(size_t)ea.x * 32 + lane];
                float2 hb = t2[(size_t)eb.x * 32 + lane];
                float wa = __int_as_float(ea.y), wb = __int_as_float(eb.y);
                a0.x += wa * ha.x; a0.y += wa * ha.y;
                a1.x += wb * hb.x; a1.y += wb * hb.y;
            }
            if (e < s1) {
                int2 ea = g_edges[e];
                float2 ha = t2[(size_t)ea.x * 32 + lane];
                float wa = __int_as_float(ea.y);
                a0.x += wa * ha.x; a0.y += wa * ha.y;
            }
            float2 hv = t2[(size_t)v * 32 + lane];
            float r0 = a0.x + a1.x + ws * hv.x + bs[2 * lane];
            float r1 = a0.y + a1.y + ws * hv.y + bs[2 * lane + 1];
            Hs[(w * 8 + i) * STR + 2 * lane]     = fmaxf(r0, 0.f);
            Hs[(w * 8 + i) * STR + 2 * lane + 1] = fmaxf(r1, 0.f);
        }
    } else {  // FIN == 32
        for (int i = 0; i < 8; i++) {
            int v = base + w * 8 + i;
            if (v >= n) break;
            int s0 = g_rowstart[v], s1 = g_rowstart[v + 1];
            float dv = g_dinv[v], ws = dv * dv;
            float a0 = 0.f, a1 = 0.f;
            int e = s0;
            for (; e + 1 < s1; e += 2) {
                int2 ea = g_edges[e], eb = g_edges[e + 1];
                a0 += __int_as_float(ea.y) * tin[(size_t)ea.x * 32 + lane];
                a1 += __int_as_float(eb.y) * tin[(size_t)eb.x * 32 + lane];
            }
            if (e < s1) {
                int2 ea = g_edges[e];
                a0 += __int_as_float(ea.y) * tin[(size_t)ea.x * 32 + lane];
            }
            float r = a0 + a1 + ws * tin[(size_t)v * 32 + lane] + bs[lane];
            Hs[(w * 8 + i) * STR + lane] = fmaxf(r, 0.f);
        }
    }
    __syncthreads();

    // Phase B: 64x FIN @ FIN x FOUT from smem
    constexpr int JT = FOUT / 4;  // 8 (FOUT=32) or 4 (FOUT=16)
    int nd = tid & 63, jh = tid >> 6;
    int j0 = jh * JT;
    float acc[JT];
#pragma unroll
    for (int q = 0; q < JT; q++) acc[q] = 0.f;
    for (int k = 0; k < FIN; k++) {
        float hv = Hs[nd * STR + k];
        const float4* w4 = (const float4*)&Ws[k * FOUT + j0];
#pragma unroll
        for (int q4 = 0; q4 < JT / 4; q4++) {
            float4 w = w4[q4];
            acc[q4 * 4 + 0] += hv * w.x;
            acc[q4 * 4 + 1] += hv * w.y;
            acc[q4 * 4 + 2] += hv * w.z;
            acc[q4 * 4 + 3] += hv * w.w;
        }
    }
    int v = base + nd;
    if (v < n) {
        float4* o = (float4*)(outp + (size_t)v * FOUT + j0);
#pragma unroll
        for (int q4 = 0; q4 < JT / 4; q4++)
            o[q4] = make_float4(2.f * acc[q4 * 4 + 0], 2.f * acc[q4 * 4 + 1],
                                2.f * acc[q4 * 4 + 2], 2.f * acc[q4 * 4 + 3]);
    }
}

// final layer agg (dim 16) fused with block-local pooling; batch sorted -> few graphs/block
__global__ void __launch_bounds__(256)
k_aggpool(const float* __restrict__ tin, const float* __restrict__ bias,
          const void* batch, int n) {
    __shared__ float spool[GMAX * 16];
    __shared__ float scnt[GMAX];
    __shared__ int sgmin, sgmax;
    int tid = threadIdx.x;
    for (int i = tid; i < GMAX * 16; i += 256) spool[i] = 0.f;
    if (tid < GMAX) scnt[tid] = 0.f;
    if (tid == 0) { sgmin = GMAX; sgmax = -1; }
    __syncthreads();
    int grp = tid >> 4, lane = tid & 15;
    int v = blockIdx.x * 16 + grp;
    if (v < n) {
        int s0 = g_rowstart[v], s1 = g_rowstart[v + 1];
        float dv = g_dinv[v], ws = dv * dv;
        float a0 = 0.f, a1 = 0.f;
        int e = s0;
        for (; e + 1 < s1; e += 2) {
            int2 ea = g_edges[e], eb = g_edges[e + 1];
            a0 += __int_as_float(ea.y) * tin[(size_t)ea.x * 16 + lane];
            a1 += __int_as_float(eb.y) * tin[(size_t)eb.x * 16 + lane];
        }
        if (e < s1) {
            int2 ea = g_edges[e];
            a0 += __int_as_float(ea.y) * tin[(size_t)ea.x * 16 + lane];
        }
        float h = fmaxf(a0 + a1 + ws * tin[(size_t)v * 16 + lane] + bias[lane], 0.f);
        int g = load_idx(batch, v, g_is64);
        atomicAdd(&spool[g * 16 + lane], h);
        if (lane == 0) {
            atomicAdd(&scnt[g], 1.f);
            atomicMin(&sgmin, g);
            atomicMax(&sgmax, g);
        }
    }
    __syncthreads();
    int lo = sgmin, hi = sgmax;
    if (hi >= lo) {
        int rows = hi - lo + 1;
        for (int i = tid; i < rows * 16; i += 256) {
            float val = spool[(lo + i / 16) * 16 + (i & 15)];
            if (val != 0.f) atomicAdd(&g_pool[(lo + i / 16) * 16 + (i & 15)], val);
        }
        for (int i = tid; i < rows; i += 256) {
            float c = scnt[lo + i];
            if (c != 0.f) atomicAdd(&g_cnt[lo + i], c);
        }
    }
}

__global__ void k_final(const float* __restrict__ fc1w, const float* __restrict__ fc1b,
                        const float* __restrict__ fc2w, const float* __restrict__ fc2b,
                        float* __restrict__ out, int G) {
    int g = threadIdx.x;
    if (g >= G) return;
    float c = fmaxf(g_cnt[g], 1.f);
    float p[16];
#pragma unroll
    for (int j = 0; j < 16; j++) p[j] = g_pool[g * 16 + j] / c;
    float z[8];
#pragma unroll
    for (int i = 0; i < 8; i++) {
        float a = fc1b[i];
#pragma unroll
        for (int j = 0; j < 16; j++) a += p[j] * fc1w[j * 8 + i];
        z[i] = fmaxf(a, 0.f);
    }
#pragma unroll
    for (int o = 0; o < 4; o++) {
        float a = fc2b[o];
#pragma unroll
        for (int i = 0; i < 8; i++) a += z[i] * fc2w[i * 4 + o];
        out[g * 4 + o] = a;
    }
}

// ------------------------------- host -------------------------------
extern "C" void kernel_launch(void* const* d_in, const int* in_sizes, int n_in,
                              void* d_out, int out_size) {
    const float* x   = (const float*)d_in[0];
    const void*  ei  = d_in[1];
    const void*  bat = d_in[2];
    const float* W0 = (const float*)d_in[3];  const float* b0 = (const float*)d_in[4];
    const float* W1 = (const float*)d_in[5];  const float* b1 = (const float*)d_in[6];
    const float* W2 = (const float*)d_in[7];  const float* b2 = (const float*)d_in[8];
    const float* W3 = (const float*)d_in[9];  const float* b3 = (const float*)d_in[10];
    const float* fc1w = (const float*)d_in[11]; const float* fc1b = (const float*)d_in[12];
    const float* fc2w = (const float*)d_in[13]; const float* fc2b = (const float*)d_in[14];
    float* out = (float*)d_out;

    int N = in_sizes[0] / 3;
    int E = in_sizes[1] / 2;
    int G = out_size / 4;
    if (N > NMAX || E > EMAX || G > GMAX) return;

    void *ph = nullptr, *pt = nullptr;
    cudaGetSymbolAddress(&ph, g_h);
    cudaGetSymbolAddress(&pt, g_t);
    float* H = (float*)ph;   // t2 (N x 32)
    float* T = (float*)pt;   // t1 (N x 64) then t3 (N x 16)

    int gN = (N + 255) / 256;
    int gE = (E + 255) / 256;
    int nb = (N + 1023) / 1024;

    k_init<<<gN, 256>>>(ei, N);
    k_hist<<<gE, 256>>>(ei, E);
    k_scan1<<<nb, 256>>>(N);
    k_scan2<<<1, 128>>>(nb, N);
    k_scan3<<<nb, 256>>>(N);
    k_scatter<<<gE, 256>>>(ei, E);

    k_agg0<<<gN, 256>>>(x, N);                              // Agg(x) at dim 3
    k_l01<<<(N + 255) / 256, 128>>>(W0, b0, W1, N);         // -> t1 in g_t
    k_fused<64, 32><<<(N + 63) / 64, 256>>>(T, b1, W2, H, N);  // t1 -> t2
    k_fused<32, 16><<<(N + 63) / 64, 256>>>(H, b2, W3, T, N);  // t2 -> t3
    k_aggpool<<<(N + 15) / 16, 256>>>(T, b3, bat, N);       // t3 -> pooled sums
    k_final<<<1, 64>>>(fc1w, fc1b, fc2w, fc2b, out, G);
}

// round 3
// speedup vs baseline: 2.7390x; 1.1149x over previous
#include <cuda_runtime.h>
#include <cuda_fp16.h>
#include <cstdint>
#include <cstddef>

#define NMAX 100000
#define EMAX 1600000
#define GMAX 64
#define NB_MAX 128

// -------- device scratch --------
__device__ __half2 g_t1[(size_t)NMAX * 32];  // t1: N x 64 fp16
__device__ __half2 g_t2[(size_t)NMAX * 16];  // t2: N x 32 fp16
__device__ __half2 g_t3[(size_t)NMAX * 8];   // t3: N x 16 fp16
__device__ __half2 g_xh[(size_t)NMAX * 2];   // x padded to half4
__device__ float   g_a[(size_t)NMAX * 4];    // aggregated x (N x 4) fp32
__device__ int2    g_edges[EMAX];            // {src, norm-as-float-bits}, grouped by dst
__device__ int     g_rowstart[NMAX + 1];
__device__ int     g_cursor[NMAX];
__device__ int     g_hist[NMAX];
__device__ float   g_dinv[NMAX];
__device__ float   g_pool[GMAX * 16];
__device__ float   g_cnt[GMAX];
__device__ int     g_bsum[NB_MAX];
__device__ int     g_boff[NB_MAX];
__device__ int     g_is64;

__device__ __forceinline__ int load_idx(const void* p, int i, int is64) {
    if (is64) return (int)__ldg((const long long*)p + i);
    return __ldg((const int*)p + i);
}

// init hist/pool/cnt, convert x -> half4, dtype detection
__global__ void k_init(const void* ei, const float* __restrict__ x, int n) {
    int i = blockIdx.x * blockDim.x + threadIdx.x;
    if (i < n) {
        g_hist[i] = 0;
        float x0 = x[3 * (size_t)i], x1 = x[3 * (size_t)i + 1], x2 = x[3 * (size_t)i + 2];
        g_xh[2 * (size_t)i]     = __floats2half2_rn(x0, x1);
        g_xh[2 * (size_t)i + 1] = __floats2half2_rn(x2, 0.f);
    }
    if (i < GMAX * 16) g_pool[i] = 0.f;
    if (i < GMAX) g_cnt[i] = 0.f;
    if (blockIdx.x == 0 && threadIdx.x < 32) {
        const int* p = (const int*)ei;
        int v = p[2 * threadIdx.x + 1];
        unsigned any = __ballot_sync(0xffffffffu, v != 0);
        if (threadIdx.x == 0) g_is64 = (any == 0) ? 1 : 0;
    }
}

__global__ void k_hist(const void* ei, int E) {
    int e = blockIdx.x * blockDim.x + threadIdx.x;
    if (e >= E) return;
    int d = load_idx(ei, E + e, g_is64);
    atomicAdd(&g_hist[d], 1);
}

// ---- 3-phase scan (block=256, 1024 elems/block) ----
__global__ void k_scan1(int n) {
    __shared__ int sh[256];
    int base = blockIdx.x * 1024 + threadIdx.x * 4;
    int s = 0;
#pragma unroll
    for (int q = 0; q < 4; q++) { int i = base + q; if (i < n) s += g_hist[i]; }
    sh[threadIdx.x] = s;
    __syncthreads();
    for (int off = 128; off > 0; off >>= 1) {
        if (threadIdx.x < off) sh[threadIdx.x] += sh[threadIdx.x + off];
        __syncthreads();
    }
    if (threadIdx.x == 0) g_bsum[blockIdx.x] = sh[0];
}

__global__ void k_scan2(int nb, int n) {
    __shared__ int sh[128];
    int t = threadIdx.x;
    int v = (t < nb) ? g_bsum[t] : 0;
    sh[t] = v;
    __syncthreads();
    for (int off = 1; off < 128; off <<= 1) {
        int u = (t >= off) ? sh[t - off] : 0;
        __syncthreads();
        sh[t] += u;
        __syncthreads();
    }
    if (t < nb) g_boff[t] = sh[t] - v;
    if (t == nb - 1) g_rowstart[n] = sh[t];   // == E
}

__global__ void k_scan3(int n) {
    __shared__ int sh[256];
    int t = threadIdx.x;
    int base = blockIdx.x * 1024 + t * 4;
    int h[4]; int s = 0;
#pragma unroll
    for (int q = 0; q < 4; q++) { int i = base + q; h[q] = (i < n) ? g_hist[i] : 0; s += h[q]; }
    sh[t] = s;
    __syncthreads();
    for (int off = 1; off < 256; off <<= 1) {
        int u = (t >= off) ? sh[t - off] : 0;
        __syncthreads();
        sh[t] += u;
        __syncthreads();
    }
    int off0 = g_boff[blockIdx.x] + sh[t] - s;
#pragma unroll
    for (int q = 0; q < 4; q++) {
        int i = base + q;
        if (i < n) {
            g_rowstart[i] = off0;
            g_cursor[i]   = off0;
            g_dinv[i]     = rsqrtf((float)(h[q] + 1));
            off0 += h[q];
        }
    }
}

__global__ void k_scatter(const void* ei, int E) {
    int e = blockIdx.x * blockDim.x + threadIdx.x;
    if (e >= E) return;
    int is64 = g_is64;
    int s = load_idx(ei, e, is64);
    int d = load_idx(ei, E + e, is64);
    int pos = atomicAdd(&g_cursor[d], 1);
    g_edges[pos] = make_int2(s, __float_as_int(g_dinv[s] * g_dinv[d]));
}

// aggregate x (half4) at dim 3 -> g_a fp32 (stride 4)
__global__ void k_agg0(int n) {
    int v = blockIdx.x * blockDim.x + threadIdx.x;
    if (v >= n) return;
    int s0 = g_rowstart[v], s1 = g_rowstart[v + 1];
    const uint2* xp = (const uint2*)g_xh;
    float a0 = 0.f, a1 = 0.f, a2 = 0.f, b0 = 0.f, b1 = 0.f, b2 = 0.f;
    int e = s0;
    for (; e + 1 < s1; e += 2) {
        int2 ea = g_edges[e], eb = g_edges[e + 1];
        float wa = __int_as_float(ea.y), wb = __int_as_float(eb.y);
        uint2 ra = xp[ea.x], rb = xp[eb.x];
        float2 fa = __half22float2(*(__half2*)&ra.x);
        float  fa2 = __low2float(*(__half2*)&ra.y);
        float2 fb = __half22float2(*(__half2*)&rb.x);
        float  fb2 = __low2float(*(__half2*)&rb.y);
        a0 += wa * fa.x; a1 += wa * fa.y; a2 += wa * fa2;
        b0 += wb * fb.x; b1 += wb * fb.y; b2 += wb * fb2;
    }
    if (e < s1) {
        int2 ea = g_edges[e];
        float wa = __int_as_float(ea.y);
        uint2 ra = xp[ea.x];
        float2 fa = __half22float2(*(__half2*)&ra.x);
        float  fa2 = __low2float(*(__half2*)&ra.y);
        a0 += wa * fa.x; a1 += wa * fa.y; a2 += wa * fa2;
    }
    float dv = g_dinv[v], ws = dv * dv;
    uint2 rs = xp[v];
    float2 fs = __half22float2(*(__half2*)&rs.x);
    float  fs2 = __low2float(*(__half2*)&rs.y);
    *(float4*)(g_a + 4 * (size_t)v) =
        make_float4(a0 + b0 + ws * fs.x, a1 + b1 + ws * fs.y, a2 + b2 + ws * fs2, 0.f);
}

// fused layers 0+1: t1[v] = 2 * relu(aggx[v]·W0 + b0) · W1  -> fp16
__global__ void __launch_bounds__(128)
k_l01(const float* __restrict__ W0, const float* __restrict__ b0,
      const float* __restrict__ W1, int n) {
    __shared__ float4 W0c[128];
    __shared__ float  W1s[128 * 64];
    int tid = threadIdx.x;
    W0c[tid] = make_float4(W0[tid], W0[128 + tid], W0[256 + tid], b0[tid]);
    for (int i = tid; i < 128 * 64; i += 128) W1s[i] = W1[i];
    __syncthreads();
    int t6 = tid & 63, jh = tid >> 6;
    int base = blockIdx.x * 256 + t6 * 4;
    float4 a[4];
#pragma unroll
    for (int p = 0; p < 4; p++) {
        int v = base + p;
        a[p] = (v < n) ? *(const float4*)(g_a + 4 * (size_t)v) : make_float4(0, 0, 0, 0);
    }
    float acc[4][32];
#pragma unroll
    for (int p = 0; p < 4; p++)
#pragma unroll
        for (int q = 0; q < 32; q++) acc[p][q] = 0.f;

    const float4* W1s4 = (const float4*)W1s;
    for (int k = 0; k < 128; k++) {
        float4 wc = W0c[k];
        float hh[4];
#pragma unroll
        for (int p = 0; p < 4; p++)
            hh[p] = fmaxf(fmaf(a[p].x, wc.x, fmaf(a[p].y, wc.y, fmaf(a[p].z, wc.z, wc.w))), 0.f);
        const float4* wr = W1s4 + k * 16 + jh * 8;
#pragma unroll
        for (int q = 0; q < 8; q++) {
            float4 w = wr[q];
#pragma unroll
            for (int p = 0; p < 4; p++) {
                acc[p][q * 4 + 0] += hh[p] * w.x;
                acc[p][q * 4 + 1] += hh[p] * w.y;
                acc[p][q * 4 + 2] += hh[p] * w.z;
                acc[p][q * 4 + 3] += hh[p] * w.w;
            }
        }
    }
#pragma unroll
    for (int p = 0; p < 4; p++) {
        int v = base + p;
        if (v < n) {
            // pack 32 floats -> 16 half2 -> 2x uint4
            uint4* o = (uint4*)(g_t1 + (size_t)v * 32 + jh * 16);
#pragma unroll
            for (int u = 0; u < 2; u++) {
                uint4 pk;
                __half2 h0 = __floats2half2_rn(2.f * acc[p][u * 16 + 0], 2.f * acc[p][u * 16 + 1]);
                __half2 h1 = __floats2half2_rn(2.f * acc[p][u * 16 + 2], 2.f * acc[p][u * 16 + 3]);
                __half2 h2 = __floats2half2_rn(2.f * acc[p][u * 16 + 4], 2.f * acc[p][u * 16 + 5]);
                __half2 h3 = __floats2half2_rn(2.f * acc[p][u * 16 + 6], 2.f * acc[p][u * 16 + 7]);
                pk.x = *(uint32_t*)&h0; pk.y = *(uint32_t*)&h1;
                pk.z = *(uint32_t*)&h2; pk.w = *(uint32_t*)&h3;
                o[u * 2] = pk;
                __half2 h4 = __floats2half2_rn(2.f * acc[p][u * 16 + 8], 2.f * acc[p][u * 16 + 9]);
                __half2 h5 = __floats2half2_rn(2.f * acc[p][u * 16 + 10], 2.f * acc[p][u * 16 + 11]);
                __half2 h6 = __floats2half2_rn(2.f * acc[p][u * 16 + 12], 2.f * acc[p][u * 16 + 13]);
                __half2 h7 = __floats2half2_rn(2.f * acc[p][u * 16 + 14], 2.f * acc[p][u * 16 + 15]);
                pk.x = *(uint32_t*)&h4; pk.y = *(uint32_t*)&h5;
                pk.z = *(uint32_t*)&h6; pk.w = *(uint32_t*)&h7;
                o[u * 2 + 1] = pk;
            }
        }
    }
}

// fused agg(64) + GEMM(64->32): h1 = relu(Agg(t1)+b1); t2 = 2*h1@W2 (fp16 out)
__global__ void __launch_bounds__(256)
k_f1(const float* __restrict__ bias, const float* __restrict__ Wg, int n) {
    constexpr int STR = 65;
    __shared__ float Hs[64 * STR];
    __shared__ float Ws[64 * 32];
    __shared__ float bs[64];
    int tid = threadIdx.x;
    for (int i = tid; i < 64 * 32; i += 256) Ws[i] = Wg[i];
    if (tid < 64) bs[tid] = bias[tid];
    int w = tid >> 5, lane = tid & 31;
    int base = blockIdx.x * 64;

    for (int i = 0; i < 8; i++) {
        int v = base + w * 8 + i;
        if (v >= n) break;
        int s0 = g_rowstart[v], s1 = g_rowstart[v + 1];
        float dv = g_dinv[v], ws = dv * dv;
        float2 a0 = make_float2(0.f, 0.f), a1 = make_float2(0.f, 0.f);
        int e = s0;
        for (; e + 1 < s1; e += 2) {
            int2 ea = g_edges[e], eb = g_edges[e + 1];
            float2 ha = __half22float2(g_t1[(size_t)ea.x * 32 + lane]);
            float2 hb = __half22float2(g_t1[(size_t)eb.x * 32 + lane]);
            float wa = __int_as_float(ea.y), wb = __int_as_float(eb.y);
            a0.x += wa * ha.x; a0.y += wa * ha.y;
            a1.x += wb * hb.x; a1.y += wb * hb.y;
        }
        if (e < s1) {
            int2 ea = g_edges[e];
            float2 ha = __half22float2(g_t1[(size_t)ea.x * 32 + lane]);
            float wa = __int_as_float(ea.y);
            a0.x += wa * ha.x; a0.y += wa * ha.y;
        }
        float2 hv = __half22float2(g_t1[(size_t)v * 32 + lane]);
        Hs[(w * 8 + i) * STR + 2 * lane]     = fmaxf(a0.x + a1.x + ws * hv.x + bs[2 * lane], 0.f);
        Hs[(w * 8 + i) * STR + 2 * lane + 1] = fmaxf(a0.y + a1.y + ws * hv.y + bs[2 * lane + 1], 0.f);
    }
    __syncthreads();

    // 64 x 64 @ 64 x 32 ; thread: nd (0..63) x jh (0..3) -> 8 outputs
    int nd = tid & 63, jh = tid >> 6;
    int j0 = jh * 8;
    float acc[8];
#pragma unroll
    for (int q = 0; q < 8; q++) acc[q] = 0.f;
    for (int k = 0; k < 64; k++) {
        float hv = Hs[nd * STR + k];
        const float4* w4 = (const float4*)&Ws[k * 32 + j0];
        float4 wA = w4[0], wB = w4[1];
        acc[0] += hv * wA.x; acc[1] += hv * wA.y; acc[2] += hv * wA.z; acc[3] += hv * wA.w;
        acc[4] += hv * wB.x; acc[5] += hv * wB.y; acc[6] += hv * wB.z; acc[7] += hv * wB.w;
    }
    int v = base + nd;
    if (v < n) {
        uint4 pk;
        __half2 h0 = __floats2half2_rn(2.f * acc[0], 2.f * acc[1]);
        __half2 h1 = __floats2half2_rn(2.f * acc[2], 2.f * acc[3]);
        __half2 h2 = __floats2half2_rn(2.f * acc[4], 2.f * acc[5]);
        __half2 h3 = __floats2half2_rn(2.f * acc[6], 2.f * acc[7]);
        pk.x = *(uint32_t*)&h0; pk.y = *(uint32_t*)&h1;
        pk.z = *(uint32_t*)&h2; pk.w = *(uint32_t*)&h3;
        *(uint4*)(g_t2 + (size_t)v * 16 + jh * 4) = pk;
    }
}

// fused agg(32) + GEMM(32->16): h2 = relu(Agg(t2)+b2); t3 = 2*h2@W3 (fp16 out)
__global__ void __launch_bounds__(256)
k_f2(const float* __restrict__ bias, const float* __restrict__ Wg, int n) {
    constexpr int STR = 33;
    __shared__ float Hs[64 * STR];
    __shared__ float Ws[32 * 16];
    __shared__ float bs[32];
    int tid = threadIdx.x;
    for (int i = tid; i < 32 * 16; i += 256) Ws[i] = Wg[i];
    if (tid < 32) bs[tid] = bias[tid];
    int w = tid >> 5, lane = tid & 31;
    int hid = lane >> 4, fl = lane & 15;    // two 16-lane halves process alternate edges
    int base = blockIdx.x * 64;

    for (int i = 0; i < 8; i++) {
        int v = base + w * 8 + i;
        if (v >= n) break;
        int s0 = g_rowstart[v], s1 = g_rowstart[v + 1];
        float2 acc = make_float2(0.f, 0.f);
        for (int e = s0 + hid; e < s1; e += 2) {
            int2 ed = g_edges[e];
            float wt = __int_as_float(ed.y);
            float2 hv = __half22float2(g_t2[(size_t)ed.x * 16 + fl]);
            acc.x += wt * hv.x; acc.y += wt * hv.y;
        }
        acc.x += __shfl_down_sync(0xffffffffu, acc.x, 16);
        acc.y += __shfl_down_sync(0xffffffffu, acc.y, 16);
        if (hid == 0) {
            float dv = g_dinv[v], ws = dv * dv;
            float2 hv = __half22float2(g_t2[(size_t)v * 16 + fl]);
            Hs[(w * 8 + i) * STR + 2 * fl]     = fmaxf(acc.x + ws * hv.x + bs[2 * fl], 0.f);
            Hs[(w * 8 + i) * STR + 2 * fl + 1] = fmaxf(acc.y + ws * hv.y + bs[2 * fl + 1], 0.f);
        }
    }
    __syncthreads();

    // 64 x 32 @ 32 x 16 ; thread: nd x jh(0..3) -> 4 outputs
    int nd = tid & 63, jh = tid >> 6;
    int j0 = jh * 4;
    float acc[4] = {0.f, 0.f, 0.f, 0.f};
    for (int k = 0; k < 32; k++) {
        float hv = Hs[nd * STR + k];
        float4 wv = *(const float4*)&Ws[k * 16 + j0];
        acc[0] += hv * wv.x; acc[1] += hv * wv.y; acc[2] += hv * wv.z; acc[3] += hv * wv.w;
    }
    int v = base + nd;
    if (v < n) {
        uint2 pk;
        __half2 h0 = __floats2half2_rn(2.f * acc[0], 2.f * acc[1]);
        __half2 h1 = __floats2half2_rn(2.f * acc[2], 2.f * acc[3]);
        pk.x = *(uint32_t*)&h0; pk.y = *(uint32_t*)&h1;
        *(uint2*)(g_t3 + (size_t)v * 8 + jh * 2) = pk;
    }
}

// final agg (dim 16 fp16, 8 threads/node) fused with block-local pooling
__global__ void __launch_bounds__(256)
k_aggpool(const float* __restrict__ bias, const void* batch, int n) {
    __shared__ float spool[GMAX * 16];
    __shared__ float scnt[GMAX];
    __shared__ int sgmin, sgmax;
    int tid = threadIdx.x;
    for (int i = tid; i < GMAX * 16; i += 256) spool[i] = 0.f;
    if (tid < GMAX) scnt[tid] = 0.f;
    if (tid == 0) { sgmin = GMAX; sgmax = -1; }
    __syncthreads();
    int grp = tid >> 3, lane8 = tid & 7;     // 32 nodes per block
    int v = blockIdx.x * 32 + grp;
    if (v < n) {
        int s0 = g_rowstart[v], s1 = g_rowstart[v + 1];
        float dv = g_dinv[v], ws = dv * dv;
        float2 a0 = make_float2(0.f, 0.f), a1 = make_float2(0.f, 0.f);
        int e = s0;
        for (; e + 1 < s1; e += 2) {
            int2 ea = g_edges[e], eb = g_edges[e + 1];
            float2 ha = __half22float2(g_t3[(size_t)ea.x * 8 + lane8]);
            float2 hb = __half22float2(g_t3[(size_t)eb.x * 8 + lane8]);
            float wa = __int_as_float(ea.y), wb = __int_as_float(eb.y);
            a0.x += wa * ha.x; a0.y += wa * ha.y;
            a1.x += wb * hb.x; a1.y += wb * hb.y;
        }
        if (e < s1) {
            int2 ea = g_edges[e];
            float2 ha = __half22float2(g_t3[(size_t)ea.x * 8 + lane8]);
            float wa = __int_as_float(ea.y);
            a0.x += wa * ha.x; a0.y += wa * ha.y;
        }
        float2 hv = __half22float2(g_t3[(size_t)v * 8 + lane8]);
        float h0 = fmaxf(a0.x + a1.x + ws * hv.x + bias[2 * lane8], 0.f);
        float h1 = fmaxf(a0.y + a1.y + ws * hv.y + bias[2 * lane8 + 1], 0.f);
        int g = load_idx(batch, v, g_is64);
        atomicAdd(&spool[g * 16 + 2 * lane8], h0);
        atomicAdd(&spool[g * 16 + 2 * lane8 + 1], h1);
        if (lane8 == 0) {
            atomicAdd(&scnt[g], 1.f);
            atomicMin(&sgmin, g);
            atomicMax(&sgmax, g);
        }
    }
    __syncthreads();
    int lo = sgmin, hi = sgmax;
    if (hi >= lo) {
        int rows = hi - lo + 1;
        for (int i = tid; i < rows * 16; i += 256) {
            float val = spool[(lo + i / 16) * 16 + (i & 15)];
            if (val != 0.f) atomicAdd(&g_pool[(lo + i / 16) * 16 + (i & 15)], val);
        }
        for (int i = tid; i < rows; i += 256) {
            float c = scnt[lo + i];
            if (c != 0.f) atomicAdd(&g_cnt[lo + i], c);
        }
    }
}

__global__ void k_final(const float* __restrict__ fc1w, const float* __restrict__ fc1b,
                        const float* __restrict__ fc2w, const float* __restrict__ fc2b,
                        float* __restrict__ out, int G) {
    int g = threadIdx.x;
    if (g >= G) return;
    float c = fmaxf(g_cnt[g], 1.f);
    float p[16];
#pragma unroll
    for (int j = 0; j < 16; j++) p[j] = g_pool[g * 16 + j] / c;
    float z[8];
#pragma unroll
    for (int i = 0; i < 8; i++) {
        float a = fc1b[i];
#pragma unroll
        for (int j = 0; j < 16; j++) a += p[j] * fc1w[j * 8 + i];
        z[i] = fmaxf(a, 0.f);
    }
#pragma unroll
    for (int o = 0; o < 4; o++) {
        float a = fc2b[o];
#pragma unroll
        for (int i = 0; i < 8; i++) a += z[i] * fc2w[i * 4 + o];
        out[g * 4 + o] = a;
    }
}

// ------------------------------- host -------------------------------
extern "C" void kernel_launch(void* const* d_in, const int* in_sizes, int n_in,
                              void* d_out, int out_size) {
    const float* x   = (const float*)d_in[0];
    const void*  ei  = d_in[1];
    const void*  bat = d_in[2];
    const float* W0 = (const float*)d_in[3];  const float* b0 = (const float*)d_in[4];
    const float* W1 = (const float*)d_in[5];  const float* b1 = (const float*)d_in[6];
    const float* W2 = (const float*)d_in[7];  const float* b2 = (const float*)d_in[8];
    const float* W3 = (const float*)d_in[9];  const float* b3 = (const float*)d_in[10];
    const float* fc1w = (const float*)d_in[11]; const float* fc1b = (const float*)d_in[12];
    const float* fc2w = (const float*)d_in[13]; const float* fc2b = (const float*)d_in[14];
    float* out = (float*)d_out;

    int N = in_sizes[0] / 3;
    int E = in_sizes[1] / 2;
    int G = out_size / 4;
    if (N > NMAX || E > EMAX || G > GMAX) return;

    int gN = (N + 255) / 256;
    int gE = (E + 255) / 256;
    int nb = (N + 1023) / 1024;

    k_init<<<gN, 256>>>(ei, x, N);
    k_hist<<<gE, 256>>>(ei, E);
    k_scan1<<<nb, 256>>>(N);
    k_scan2<<<1, 128>>>(nb, N);
    k_scan3<<<nb, 256>>>(N);
    k_scatter<<<gE, 256>>>(ei, E);

    k_agg0<<<gN, 256>>>(N);                         // Agg(x) at dim 3 (fp16 gathers)
    k_l01<<<(N + 255) / 256, 128>>>(W0, b0, W1, N); // -> t1 fp16
    k_f1<<<(N + 63) / 64, 256>>>(b1, W2, N);        // t1 -> t2 fp16
    k_f2<<<(N + 63) / 64, 256>>>(b2, W3, N);        // t2 -> t3 fp16
    k_aggpool<<<(N + 31) / 32, 256>>>(b3, bat, N);  // t3 -> pooled sums
    k_final<<<1, 64>>>(fc1w, fc1b, fc2w, fc2b, out, G);
}

// round 4
// speedup vs baseline: 2.9313x; 1.0702x over previous
#include <cuda_runtime.h>
#include <cuda_fp16.h>
#include <cstdint>
#include <cstddef>

#define NMAX 100000
#define EMAX 1600000
#define GMAX 64
#define NB_MAX 128

// -------- device scratch --------
__device__ __half2 g_t1[(size_t)NMAX * 32];  // u1: N x 64 fp16 (dinv-scaled)
__device__ __half2 g_t2[(size_t)NMAX * 16];  // u2: N x 32 fp16
__device__ __half2 g_t3[(size_t)NMAX * 8];   // u3: N x 16 fp16
__device__ __half2 g_xh[(size_t)NMAX * 2];   // ux = dinv*x, padded half4
__device__ float   g_a[(size_t)NMAX * 4];    // aggregated x (N x 4) fp32
__device__ int     g_esrc[EMAX];             // src only, grouped by dst
__device__ int     g_rowstart[NMAX + 1];
__device__ int     g_cursor[NMAX];
__device__ int     g_hist[NMAX];
__device__ float   g_dinv[NMAX];
__device__ float   g_pool[GMAX * 16];
__device__ float   g_cnt[GMAX];
__device__ int     g_bsum[NB_MAX];
__device__ int     g_boff[NB_MAX];
__device__ int     g_is64;

__device__ __forceinline__ int load_idx(const void* p, int i, int is64) {
    if (is64) return (int)__ldg((const long long*)p + i);
    return __ldg((const int*)p + i);
}

// packed f32x2 helpers
__device__ __forceinline__ unsigned long long f2fma(unsigned long long a, unsigned long long b,
                                                    unsigned long long c) {
    unsigned long long d;
    asm("fma.rn.f32x2 %0, %1, %2, %3;" : "=l"(d) : "l"(a), "l"(b), "l"(c));
    return d;
}
__device__ __forceinline__ unsigned long long f2pack(float x, float y) {
    unsigned long long r;
    asm("mov.b64 %0, {%1, %2};" : "=l"(r) : "f"(x), "f"(y));
    return r;
}
__device__ __forceinline__ float2 f2unpack(unsigned long long v) {
    float lo, hi;
    asm("mov.b64 {%0, %1}, %2;" : "=f"(lo), "=f"(hi) : "l"(v));
    return make_float2(lo, hi);
}

// init hist/pool/cnt + dtype detection
__global__ void k_init(const void* ei, int n) {
    int i = blockIdx.x * blockDim.x + threadIdx.x;
    if (i < n) g_hist[i] = 0;
    if (i < GMAX * 16) g_pool[i] = 0.f;
    if (i < GMAX) g_cnt[i] = 0.f;
    if (blockIdx.x == 0 && threadIdx.x < 32) {
        const int* p = (const int*)ei;
        int v = p[2 * threadIdx.x + 1];
        unsigned any = __ballot_sync(0xffffffffu, v != 0);
        if (threadIdx.x == 0) g_is64 = (any == 0) ? 1 : 0;
    }
}

__global__ void k_hist(const void* ei, int E) {
    int e = blockIdx.x * blockDim.x + threadIdx.x;
    if (e >= E) return;
    int d = load_idx(ei, E + e, g_is64);
    atomicAdd(&g_hist[d], 1);
}

// ---- 3-phase scan ----
__global__ void k_scan1(int n) {
    __shared__ int sh[256];
    int base = blockIdx.x * 1024 + threadIdx.x * 4;
    int s = 0;
#pragma unroll
    for (int q = 0; q < 4; q++) { int i = base + q; if (i < n) s += g_hist[i]; }
    sh[threadIdx.x] = s;
    __syncthreads();
    for (int off = 128; off > 0; off >>= 1) {
        if (threadIdx.x < off) sh[threadIdx.x] += sh[threadIdx.x + off];
        __syncthreads();
    }
    if (threadIdx.x == 0) g_bsum[blockIdx.x] = sh[0];
}

__global__ void k_scan2(int nb, int n) {
    __shared__ int sh[128];
    int t = threadIdx.x;
    int v = (t < nb) ? g_bsum[t] : 0;
    sh[t] = v;
    __syncthreads();
    for (int off = 1; off < 128; off <<= 1) {
        int u = (t >= off) ? sh[t - off] : 0;
        __syncthreads();
        sh[t] += u;
        __syncthreads();
    }
    if (t < nb) g_boff[t] = sh[t] - v;
    if (t == nb - 1) g_rowstart[n] = sh[t];
}

// scan3 also computes dinv and converts x -> ux = dinv*x (fp16 half4)
__global__ void k_scan3(const float* __restrict__ x, int n) {
    __shared__ int sh[256];
    int t = threadIdx.x;
    int base = blockIdx.x * 1024 + t * 4;
    int h[4]; int s = 0;
#pragma unroll
    for (int q = 0; q < 4; q++) { int i = base + q; h[q] = (i < n) ? g_hist[i] : 0; s += h[q]; }
    sh[t] = s;
    __syncthreads();
    for (int off = 1; off < 256; off <<= 1) {
        int u = (t >= off) ? sh[t - off] : 0;
        __syncthreads();
        sh[t] += u;
        __syncthreads();
    }
    int off0 = g_boff[blockIdx.x] + sh[t] - s;
#pragma unroll
    for (int q = 0; q < 4; q++) {
        int i = base + q;
        if (i < n) {
            g_rowstart[i] = off0;
            g_cursor[i]   = off0;
            float dv = rsqrtf((float)(h[q] + 1));
            g_dinv[i] = dv;
            float x0 = x[3 * (size_t)i], x1 = x[3 * (size_t)i + 1], x2 = x[3 * (size_t)i + 2];
            g_xh[2 * (size_t)i]     = __floats2half2_rn(dv * x0, dv * x1);
            g_xh[2 * (size_t)i + 1] = __floats2half2_rn(dv * x2, 0.f);
            off0 += h[q];
        }
    }
}

__global__ void k_scatter(const void* ei, int E) {
    int e = blockIdx.x * blockDim.x + threadIdx.x;
    if (e >= E) return;
    int is64 = g_is64;
    int s = load_idx(ei, e, is64);
    int d = load_idx(ei, E + e, is64);
    int pos = atomicAdd(&g_cursor[d], 1);
    g_esrc[pos] = s;
}

// aggregate ux at dim 3 -> g_a = dinv[v]*(sum + self) (fp32, stride 4)
__global__ void k_agg0(int n) {
    int v = blockIdx.x * blockDim.x + threadIdx.x;
    if (v >= n) return;
    int s0 = g_rowstart[v], s1 = g_rowstart[v + 1];
    const uint2* xp = (const uint2*)g_xh;
    float a0 = 0.f, a1 = 0.f, a2 = 0.f, b0 = 0.f, b1 = 0.f, b2 = 0.f;
    int e = s0;
    for (; e + 3 < s1; e += 4) {
        int sa = g_esrc[e], sb = g_esrc[e + 1], sc = g_esrc[e + 2], sd = g_esrc[e + 3];
        uint2 ra = xp[sa], rb = xp[sb], rc = xp[sc], rd = xp[sd];
        float2 fa = __half22float2(*(__half2*)&ra.x); float fa2 = __low2float(*(__half2*)&ra.y);
        float2 fb = __half22float2(*(__half2*)&rb.x); float fb2 = __low2float(*(__half2*)&rb.y);
        float2 fc = __half22float2(*(__half2*)&rc.x); float fc2 = __low2float(*(__half2*)&rc.y);
        float2 fd = __half22float2(*(__half2*)&rd.x); float fd2 = __low2float(*(__half2*)&rd.y);
        a0 += fa.x + fc.x; a1 += fa.y + fc.y; a2 += fa2 + fc2;
        b0 += fb.x + fd.x; b1 += fb.y + fd.y; b2 += fb2 + fd2;
    }
    for (; e < s1; e++) {
        uint2 ra = xp[g_esrc[e]];
        float2 fa = __half22float2(*(__half2*)&ra.x); float fa2 = __low2float(*(__half2*)&ra.y);
        a0 += fa.x; a1 += fa.y; a2 += fa2;
    }
    uint2 rs = xp[v];
    float2 fs = __half22float2(*(__half2*)&rs.x); float fs2 = __low2float(*(__half2*)&rs.y);
    float dv = g_dinv[v];
    *(float4*)(g_a + 4 * (size_t)v) =
        make_float4(dv * (a0 + b0 + fs.x), dv * (a1 + b1 + fs.y), dv * (a2 + b2 + fs2), 0.f);
}

// fused layers 0+1: u1[v] = 2*dinv[v] * relu(aggx[v]·W0+b0) · W1 -> fp16
__global__ void __launch_bounds__(128)
k_l01(const float* __restrict__ W0, const float* __restrict__ b0,
      const float* __restrict__ W1, int n) {
    __shared__ float4 W0c[128];
    __shared__ float  W1s[128 * 64];
    int tid = threadIdx.x;
    W0c[tid] = make_float4(W0[tid], W0[128 + tid], W0[256 + tid], b0[tid]);
    for (int i = tid; i < 128 * 64; i += 128) W1s[i] = W1[i];
    __syncthreads();
    int t6 = tid & 63, jh = tid >> 6;
    int base = blockIdx.x * 256 + t6 * 4;
    float4 a[4];
#pragma unroll
    for (int p = 0; p < 4; p++) {
        int v = base + p;
        a[p] = (v < n) ? *(const float4*)(g_a + 4 * (size_t)v) : make_float4(0, 0, 0, 0);
    }
    unsigned long long acc2[4][16];
#pragma unroll
    for (int p = 0; p < 4; p++)
#pragma unroll
        for (int q = 0; q < 16; q++) acc2[p][q] = 0ull;

    for (int k = 0; k < 128; k++) {
        float4 wc = W0c[k];
        unsigned long long hp2[4];
#pragma unroll
        for (int p = 0; p < 4; p++) {
            float hh = fmaxf(fmaf(a[p].x, wc.x, fmaf(a[p].y, wc.y, fmaf(a[p].z, wc.z, wc.w))), 0.f);
            hp2[p] = f2pack(hh, hh);
        }
        const ulonglong2* wr = (const ulonglong2*)(W1s + k * 64 + jh * 32);
#pragma unroll
        for (int q = 0; q < 8; q++) {
            ulonglong2 w = wr[q];
#pragma unroll
            for (int p = 0; p < 4; p++) {
                acc2[p][2 * q]     = f2fma(hp2[p], w.x, acc2[p][2 * q]);
                acc2[p][2 * q + 1] = f2fma(hp2[p], w.y, acc2[p][2 * q + 1]);
            }
        }
    }
#pragma unroll
    for (int p = 0; p < 4; p++) {
        int v = base + p;
        if (v < n) {
            float s = 2.f * g_dinv[v];
            uint4* o = (uint4*)(g_t1 + (size_t)v * 32 + jh * 16);
#pragma unroll
            for (int u = 0; u < 4; u++) {
                uint4 pk;
#pragma unroll
                for (int c = 0; c < 4; c++) {
                    float2 f = f2unpack(acc2[p][u * 4 + c]);
                    __half2 hh = __floats2half2_rn(s * f.x, s * f.y);
                    ((uint32_t*)&pk)[c] = *(uint32_t*)&hh;
                }
                o[u] = pk;
            }
        }
    }
}

// fused agg(64) + GEMM(64->32): h1 = relu(dinv*(sum u1)+b1); u2 = 2*dinv*(h1@W2)
__global__ void __launch_bounds__(256)
k_f1(const float* __restrict__ bias, const float* __restrict__ Wg, int n) {
    constexpr int STR = 65;
    __shared__ float Hs[64 * STR];
    __shared__ float Ws[64 * 32];
    __shared__ float bs[64];
    int tid = threadIdx.x;
    for (int i = tid; i < 64 * 32; i += 256) Ws[i] = Wg[i];
    if (tid < 64) bs[tid] = bias[tid];
    int w = tid >> 5, lane = tid & 31;
    int base = blockIdx.x * 64;

    for (int i = 0; i < 8; i++) {
        int v = base + w * 8 + i;
        if (v >= n) break;
        int s0 = g_rowstart[v], s1 = g_rowstart[v + 1];
        float2 p0 = make_float2(0.f, 0.f), p1 = make_float2(0.f, 0.f);
        float2 p2 = make_float2(0.f, 0.f), p3 = make_float2(0.f, 0.f);
        int e = s0;
        for (; e + 3 < s1; e += 4) {
            int sa = g_esrc[e], sb = g_esrc[e + 1], sc = g_esrc[e + 2], sd = g_esrc[e + 3];
            float2 ha = __half22float2(g_t1[(size_t)sa * 32 + lane]);
            float2 hb = __half22float2(g_t1[(size_t)sb * 32 + lane]);
            float2 hc = __half22float2(g_t1[(size_t)sc * 32 + lane]);
            float2 hd = __half22float2(g_t1[(size_t)sd * 32 + lane]);
            p0.x += ha.x; p0.y += ha.y; p1.x += hb.x; p1.y += hb.y;
            p2.x += hc.x; p2.y += hc.y; p3.x += hd.x; p3.y += hd.y;
        }
        for (; e < s1; e++) {
            float2 ha = __half22float2(g_t1[(size_t)g_esrc[e] * 32 + lane]);
            p0.x += ha.x; p0.y += ha.y;
        }
        float2 hv = __half22float2(g_t1[(size_t)v * 32 + lane]);
        float dv = g_dinv[v];
        float r0 = dv * (p0.x + p1.x + p2.x + p3.x + hv.x) + bs[2 * lane];
        float r1 = dv * (p0.y + p1.y + p2.y + p3.y + hv.y) + bs[2 * lane + 1];
        Hs[(w * 8 + i) * STR + 2 * lane]     = fmaxf(r0, 0.f);
        Hs[(w * 8 + i) * STR + 2 * lane + 1] = fmaxf(r1, 0.f);
    }
    __syncthreads();

    int nd = tid & 63, jh = tid >> 6;
    int j0 = jh * 8;
    unsigned long long acc2[4] = {0ull, 0ull, 0ull, 0ull};
    for (int k = 0; k < 64; k++) {
        float hv = Hs[nd * STR + k];
        unsigned long long h2 = f2pack(hv, hv);
        ulonglong2 wA = *(const ulonglong2*)&Ws[k * 32 + j0];
        ulonglong2 wB = *(const ulonglong2*)&Ws[k * 32 + j0 + 4];
        acc2[0] = f2fma(h2, wA.x, acc2[0]);
        acc2[1] = f2fma(h2, wA.y, acc2[1]);
        acc2[2] = f2fma(h2, wB.x, acc2[2]);
        acc2[3] = f2fma(h2, wB.y, acc2[3]);
    }
    int v = base + nd;
    if (v < n) {
        float s = 2.f * g_dinv[v];
        uint4 pk;
#pragma unroll
        for (int c = 0; c < 4; c++) {
            float2 f = f2unpack(acc2[c]);
            __half2 hh = __floats2half2_rn(s * f.x, s * f.y);
            ((uint32_t*)&pk)[c] = *(uint32_t*)&hh;
        }
        *(uint4*)(g_t2 + (size_t)v * 16 + jh * 4) = pk;
    }
}

// fused agg(32) + GEMM(32->16): h2 = relu(dinv*(sum u2)+b2); u3 = 2*dinv*(h2@W3)
__global__ void __launch_bounds__(256)
k_f2(const float* __restrict__ bias, const float* __restrict__ Wg, int n) {
    constexpr int STR = 33;
    __shared__ float Hs[64 * STR];
    __shared__ float Ws[32 * 16];
    __shared__ float bs[32];
    int tid = threadIdx.x;
    for (int i = tid; i < 32 * 16; i += 256) Ws[i] = Wg[i];
    if (tid < 32) bs[tid] = bias[tid];
    int w = tid >> 5, lane = tid & 31;
    int hid = lane >> 4, fl = lane & 15;
    int base = blockIdx.x * 64;

    for (int i = 0; i < 8; i++) {
        int v = base + w * 8 + i;
        if (v >= n) break;
        int s0 = g_rowstart[v], s1 = g_rowstart[v + 1];
        float2 p0 = make_float2(0.f, 0.f), p1 = make_float2(0.f, 0.f);
        int e = s0 + hid;
        for (; e + 2 < s1; e += 4) {
            int sa = g_esrc[e], sb = g_esrc[e + 2];
            float2 ha = __half22float2(g_t2[(size_t)sa * 16 + fl]);
            float2 hb = __half22float2(g_t2[(size_t)sb * 16 + fl]);
            p0.x += ha.x; p0.y += ha.y; p1.x += hb.x; p1.y += hb.y;
        }
        for (; e < s1; e += 2) {
            float2 ha = __half22float2(g_t2[(size_t)g_esrc[e] * 16 + fl]);
            p0.x += ha.x; p0.y += ha.y;
        }
        float ax = p0.x + p1.x, ay = p0.y + p1.y;
        ax += __shfl_down_sync(0xffffffffu, ax, 16);
        ay += __shfl_down_sync(0xffffffffu, ay, 16);
        if (hid == 0) {
            float dv = g_dinv[v];
            float2 hv = __half22float2(g_t2[(size_t)v * 16 + fl]);
            Hs[(w * 8 + i) * STR + 2 * fl]     = fmaxf(dv * (ax + hv.x) + bs[2 * fl], 0.f);
            Hs[(w * 8 + i) * STR + 2 * fl + 1] = fmaxf(dv * (ay + hv.y) + bs[2 * fl + 1], 0.f);
        }
    }
    __syncthreads();

    int nd = tid & 63, jh = tid >> 6;
    int j0 = jh * 4;
    unsigned long long acc2[2] = {0ull, 0ull};
    for (int k = 0; k < 32; k++) {
        float hv = Hs[nd * STR + k];
        unsigned long long h2 = f2pack(hv, hv);
        ulonglong2 wv = *(const ulonglong2*)&Ws[k * 16 + j0];
        acc2[0] = f2fma(h2, wv.x, acc2[0]);
        acc2[1] = f2fma(h2, wv.y, acc2[1]);
    }
    int v = base + nd;
    if (v < n) {
        float s = 2.f * g_dinv[v];
        float2 f0 = f2unpack(acc2[0]), f1 = f2unpack(acc2[1]);
        uint2 pk;
        __half2 h0 = __floats2half2_rn(s * f0.x, s * f0.y);
        __half2 h1 = __floats2half2_rn(s * f1.x, s * f1.y);
        pk.x = *(uint32_t*)&h0; pk.y = *(uint32_t*)&h1;
        *(uint2*)(g_t3 + (size_t)v * 8 + jh * 2) = pk;
    }
}

// final agg (dim 16 fp16, 8 threads/node) fused with block-local pooling
__global__ void __launch_bounds__(256)
k_aggpool(const float* __restrict__ bias, const void* batch, int n) {
    __shared__ float spool[GMAX * 16];
    __shared__ float scnt[GMAX];
    __shared__ int sgmin, sgmax;
    int tid = threadIdx.x;
    for (int i = tid; i < GMAX * 16; i += 256) spool[i] = 0.f;
    if (tid < GMAX) scnt[tid] = 0.f;
    if (tid == 0) { sgmin = GMAX; sgmax = -1; }
    __syncthreads();
    int grp = tid >> 3, lane8 = tid & 7;
    int v = blockIdx.x * 32 + grp;
    if (v < n) {
        int s0 = g_rowstart[v], s1 = g_rowstart[v + 1];
        float2 p0 = make_float2(0.f, 0.f), p1 = make_float2(0.f, 0.f);
        float2 p2 = make_float2(0.f, 0.f), p3 = make_float2(0.f, 0.f);
        int e = s0;
        for (; e + 3 < s1; e += 4) {
            int sa = g_esrc[e], sb = g_esrc[e + 1], sc = g_esrc[e + 2], sd = g_esrc[e + 3];
            float2 ha = __half22float2(g_t3[(size_t)sa * 8 + lane8]);
            float2 hb = __half22float2(g_t3[(size_t)sb * 8 + lane8]);
            float2 hc = __half22float2(g_t3[(size_t)sc * 8 + lane8]);
            float2 hd = __half22float2(g_t3[(size_t)sd * 8 + lane8]);
            p0.x += ha.x; p0.y += ha.y; p1.x += hb.x; p1.y += hb.y;
            p2.x += hc.x; p2.y += hc.y; p3.x += hd.x; p3.y += hd.y;
        }
        for (; e < s1; e++) {
            float2 ha = __half22float2(g_t3[(size_t)g_esrc[e] * 8 + lane8]);
            p0.x += ha.x; p0.y += ha.y;
        }
        float2 hv = __half22float2(g_t3[(size_t)v * 8 + lane8]);
        float dv = g_dinv[v];
        float h0 = fmaxf(dv * (p0.x + p1.x + p2.x + p3.x + hv.x) + bias[2 * lane8], 0.f);
        float h1 = fmaxf(dv * (p0.y + p1.y + p2.y + p3.y + hv.y) + bias[2 * lane8 + 1], 0.f);
        int g = load_idx(batch, v, g_is64);
        atomicAdd(&spool[g * 16 + 2 * lane8], h0);
        atomicAdd(&spool[g * 16 + 2 * lane8 + 1], h1);
        if (lane8 == 0) {
            atomicAdd(&scnt[g], 1.f);
            atomicMin(&sgmin, g);
            atomicMax(&sgmax, g);
        }
    }
    __syncthreads();
    int lo = sgmin, hi = sgmax;
    if (hi >= lo) {
        int rows = hi - lo + 1;
        for (int i = tid; i < rows * 16; i += 256) {
            float val = spool[(lo + i / 16) * 16 + (i & 15)];
            if (val != 0.f) atomicAdd(&g_pool[(lo + i / 16) * 16 + (i & 15)], val);
        }
        for (int i = tid; i < rows; i += 256) {
            float c = scnt[lo + i];
            if (c != 0.f) atomicAdd(&g_cnt[lo + i], c);
        }
    }
}

__global__ void k_final(const float* __restrict__ fc1w, const float* __restrict__ fc1b,
                        const float* __restrict__ fc2w, const float* __restrict__ fc2b,
                        float* __restrict__ out, int G) {
    int g = threadIdx.x;
    if (g >= G) return;
    float c = fmaxf(g_cnt[g], 1.f);
    float p[16];
#pragma unroll
    for (int j = 0; j < 16; j++) p[j] = g_pool[g * 16 + j] / c;
    float z[8];
#pragma unroll
    for (int i = 0; i < 8; i++) {
        float a = fc1b[i];
#pragma unroll
        for (int j = 0; j < 16; j++) a += p[j] * fc1w[j * 8 + i];
        z[i] = fmaxf(a, 0.f);
    }
#pragma unroll
    for (int o = 0; o < 4; o++) {
        float a = fc2b[o];
#pragma unroll
        for (int i = 0; i < 8; i++) a += z[i] * fc2w[i * 4 + o];
        out[g * 4 + o] = a;
    }
}

// ------------------------------- host -------------------------------
extern "C" void kernel_launch(void* const* d_in, const int* in_sizes, int n_in,
                              void* d_out, int out_size) {
    const float* x   = (const float*)d_in[0];
    const void*  ei  = d_in[1];
    const void*  bat = d_in[2];
    const float* W0 = (const float*)d_in[3];  const float* b0 = (const float*)d_in[4];
    const float* W1 = (const float*)d_in[5];  const float* b1 = (const float*)d_in[6];
    const float* W2 = (const float*)d_in[7];  const float* b2 = (const float*)d_in[8];
    const float* W3 = (const float*)d_in[9];  const float* b3 = (const float*)d_in[10];
    const float* fc1w = (const float*)d_in[11]; const float* fc1b = (const float*)d_in[12];
    const float* fc2w = (const float*)d_in[13]; const float* fc2b = (const float*)d_in[14];
    float* out = (float*)d_out;

    int N = in_sizes[0] / 3;
    int E = in_sizes[1] / 2;
    int G = out_size / 4;
    if (N > NMAX || E > EMAX || G > GMAX) return;

    int gN = (N + 255) / 256;
    int gE = (E + 255) / 256;
    int nb = (N + 1023) / 1024;

    k_init<<<gN, 256>>>(ei, N);
    k_hist<<<gE, 256>>>(ei, E);
    k_scan1<<<nb, 256>>>(N);
    k_scan2<<<1, 128>>>(nb, N);
    k_scan3<<<nb, 256>>>(x, N);
    k_scatter<<<gE, 256>>>(ei, E);

    k_agg0<<<gN, 256>>>(N);
    k_l01<<<(N + 255) / 256, 128>>>(W0, b0, W1, N);
    k_f1<<<(N + 63) / 64, 256>>>(b1, W2, N);
    k_f2<<<(N + 63) / 64, 256>>>(b2, W3, N);
    k_aggpool<<<(N + 31) / 32, 256>>>(b3, bat, N);
    k_final<<<1, 64>>>(fc1w, fc1b, fc2w, fc2b, out, G);
}